// round 1
// baseline (speedup 1.0000x reference)
#include <cuda_runtime.h>
#include <cstdint>

// Problem constants
#define NSEG 6
#define NCH  512
#define NPOS 16384     // 128*128
#define NBINS 16

// ---------------- device scratch (no allocation allowed) ----------------
__device__ unsigned g_mbits[NSEG * 512];     // bit-packed mask, 512 u32/segment
__device__ int      g_posA[NSEG * NBINS];    // bin window start (position)
__device__ int      g_posB[NSEG * NBINS];    // bin window end (exclusive)
__device__ float    g_rdenom[NSEG * NBINS];  // 1/denom per bin
__device__ float    g_ys[NSEG * NCH * NBINS];
__device__ float    g_h1[NSEG * 2048];
__device__ float    g_h2[NSEG * 512];
__device__ float    g_w0[NSEG * 512];
__device__ float    g_w1[NSEG * 256];
__device__ float    g_w2[NSEG * 128];
__device__ float    g_w3[NSEG * 64];

// ---------------- K1: mask + scan + bin boundaries ----------------
// grid = 6 blocks (one per segment), 256 threads, 64 positions/thread.
__global__ void k_prep(const int* __restrict__ parsing)
{
    const int s = blockIdx.x;
    const int tid = threadIdx.x;
    __shared__ int ssum[256];
    __shared__ int sstart[NBINS], send[NBINS];

    const int* pseg = parsing + s * 65536;   // [256,256] plane
    const int base = tid * 64;

    // pass 1: mask bits + local count. nearest 256->128 is index*2.
    int cnt = 0;
    unsigned mw0 = 0, mw1 = 0;
#pragma unroll
    for (int j = 0; j < 64; j++) {
        int p = base + j;
        int h = p >> 7, w = p & 127;
        int m = (pseg[h * 512 + (w << 1)] != 0);
        cnt += m;
        if (j < 32) mw0 |= ((unsigned)m) << j;
        else        mw1 |= ((unsigned)m) << (j - 32);
    }
    g_mbits[s * 512 + tid * 2]     = mw0;
    g_mbits[s * 512 + tid * 2 + 1] = mw1;

    ssum[tid] = cnt;
    __syncthreads();
    // inclusive Hillis-Steele scan over 256 thread sums
    for (int off = 1; off < 256; off <<= 1) {
        int v = (tid >= off) ? ssum[tid - off] : 0;
        __syncthreads();
        ssum[tid] += v;
        __syncthreads();
    }
    const int incl = ssum[tid];
    const int L    = ssum[255];
    const int exc  = incl - cnt;

    if (tid < NBINS) {
        int k  = tid;
        int st = (k * L) >> 4;                 // floor(k*L/16)
        int en = ((k + 1) * L + 15) >> 4;      // ceil((k+1)*L/16)
        sstart[k] = st;
        send[k]   = en;
        int d = en - st; if (d < 1) d = 1;
        g_rdenom[s * NBINS + k] = 1.0f / (float)d;
        g_posA[s * NBINS + k] = 0;             // default empty window
        g_posB[s * NBINS + k] = 0;
    }
    __syncthreads();

    // pass 2: walk own chunk, assign ranks, record window boundaries.
    int r = exc;
#pragma unroll 1
    for (int j = 0; j < 64; j++) {
        int m = (int)(((j < 32) ? (mw0 >> j) : (mw1 >> (j - 32))) & 1u);
        if (m) {
            int p = base + j;
            for (int k = 0; k < NBINS; k++) {
                if (r == sstart[k])     g_posA[s * NBINS + k] = p;
                if (r + 1 == send[k])   g_posB[s * NBINS + k] = p + 1;
            }
            r++;
        }
    }
}

// ---------------- K2: masked adaptive pool ----------------
// grid = NSEG*NCH blocks, 512 threads = 16 warps; warp k owns bin k.
__global__ void __launch_bounds__(512) k_pool(const float* __restrict__ xs)
{
    const int sc   = blockIdx.x;          // s*512 + c
    const int s    = sc >> 9;
    const int warp = threadIdx.x >> 5;
    const int lane = threadIdx.x & 31;

    const int lo = g_posA[s * NBINS + warp];
    const int hi = g_posB[s * NBINS + warp];

    const float4* __restrict__ x4 = (const float4*)(xs + ((size_t)sc << 14));
    const unsigned* __restrict__ mb = g_mbits + s * 512;

    float a0 = 0.f, a1 = 0.f;
    const int i1 = (hi + 3) >> 2;
    for (int i = (lo >> 2) + lane; i < i1; i += 32) {
        float4 v = x4[i];
        unsigned nib = mb[i >> 3] >> ((i & 7) << 2);
        int pb = i << 2;
        float t0 = ((nib & 1u) && pb     >= lo && pb     < hi) ? v.x : 0.f;
        float t1 = ((nib & 2u) && pb + 1 >= lo && pb + 1 < hi) ? v.y : 0.f;
        float t2 = ((nib & 4u) && pb + 2 >= lo && pb + 2 < hi) ? v.z : 0.f;
        float t3 = ((nib & 8u) && pb + 3 >= lo && pb + 3 < hi) ? v.w : 0.f;
        a0 += t0 + t2;
        a1 += t1 + t3;
    }
    float acc = a0 + a1;
#pragma unroll
    for (int o = 16; o; o >>= 1) acc += __shfl_xor_sync(0xffffffffu, acc, o);
    if (lane == 0) {
        int c = sc & 511;
        g_ys[s * (NCH * NBINS) + c * NBINS + warp] = acc * g_rdenom[s * NBINS + warp];
    }
}

// ---------------- generic warp-per-row GEMV ----------------
__device__ __forceinline__ float dot4(float4 a, float4 b, float acc)
{
    acc = fmaf(a.x, b.x, acc);
    acc = fmaf(a.y, b.y, acc);
    acc = fmaf(a.z, b.z, acc);
    acc = fmaf(a.w, b.w, acc);
    return acc;
}

template <int ROWS, int KLEN, bool SEGW, bool SEGB>
__device__ __forceinline__ void gemv_body(const float* __restrict__ W,
                                          const float* __restrict__ bias,
                                          const float* __restrict__ x,
                                          float* __restrict__ y,
                                          float* __restrict__ out2, int out2off)
{
    __shared__ float4 sx[2048];               // up to klen=8192 floats (32 KB)
    constexpr int BPS = ROWS / 8;             // 8 warps per 256-thread block
    constexpr int K4  = KLEN / 4;
    const int s        = blockIdx.x / BPS;
    const int rowInSeg = (blockIdx.x % BPS) * 8 + (threadIdx.x >> 5);
    const int lane     = threadIdx.x & 31;

    const float4* __restrict__ xv = (const float4*)(x + s * KLEN);
    for (int i = threadIdx.x; i < K4; i += 256) sx[i] = xv[i];
    __syncthreads();

    const float4* __restrict__ wv =
        (const float4*)(W + (size_t)((SEGW ? s * ROWS : 0) + rowInSeg) * KLEN);

    float a0 = 0.f, a1 = 0.f;
    constexpr int ITERS = K4 / 32;            // K4 % 32 == 0 for all uses
    int t = 0;
    for (; t + 1 < ITERS; t += 2) {
        a0 = dot4(wv[lane + 32 * t],       sx[lane + 32 * t],       a0);
        a1 = dot4(wv[lane + 32 * (t + 1)], sx[lane + 32 * (t + 1)], a1);
    }
    if (t < ITERS)
        a0 = dot4(wv[lane + 32 * t], sx[lane + 32 * t], a0);

    float acc = a0 + a1;
#pragma unroll
    for (int o = 16; o; o >>= 1) acc += __shfl_xor_sync(0xffffffffu, acc, o);

    if (lane == 0) {
        float r = acc + bias[(SEGB ? s * ROWS : 0) + rowInSeg];
        y[s * ROWS + rowInSeg] = r;
        if (out2) out2[s * 960 + out2off + rowInSeg] = r;
    }
}

__global__ void __launch_bounds__(256) k_fcA(const float* __restrict__ W, const float* __restrict__ b)
{ gemv_body<2048, 8192, true, true>(W, b, g_ys, g_h1, nullptr, 0); }

__global__ void __launch_bounds__(256) k_fcB(const float* __restrict__ W, const float* __restrict__ b)
{ gemv_body<512, 2048, true, true>(W, b, g_h1, g_h2, nullptr, 0); }

__global__ void __launch_bounds__(256) k_fcC(const float* __restrict__ W, const float* __restrict__ b, float* out)
{ gemv_body<512, 512, true, true>(W, b, g_h2, g_w0, out, 0); }

__global__ void __launch_bounds__(256) k_p1(const float* __restrict__ W, const float* __restrict__ b, float* out)
{ gemv_body<256, 512, false, false>(W, b, g_w0, g_w1, out, 512); }

__global__ void __launch_bounds__(256) k_p2(const float* __restrict__ W, const float* __restrict__ b, float* out)
{ gemv_body<128, 256, false, false>(W, b, g_w1, g_w2, out, 768); }

__global__ void __launch_bounds__(256) k_p3(const float* __restrict__ W, const float* __restrict__ b, float* out)
{ gemv_body<64, 128, false, false>(W, b, g_w2, g_w3, out, 896); }

// ---------------- launch ----------------
extern "C" void kernel_launch(void* const* d_in, const int* in_sizes, int n_in,
                              void* d_out, int out_size)
{
    const float* xs      = (const float*)d_in[0];
    const int*   parsing = (const int*)  d_in[1];
    const float* fcA_w   = (const float*)d_in[2];
    const float* fcA_b   = (const float*)d_in[3];
    const float* fcB_w   = (const float*)d_in[4];
    const float* fcB_b   = (const float*)d_in[5];
    const float* fcC_w   = (const float*)d_in[6];
    const float* fcC_b   = (const float*)d_in[7];
    const float* p1_w    = (const float*)d_in[8];
    const float* p1_b    = (const float*)d_in[9];
    const float* p2_w    = (const float*)d_in[10];
    const float* p2_b    = (const float*)d_in[11];
    const float* p3_w    = (const float*)d_in[12];
    const float* p3_b    = (const float*)d_in[13];
    float* out = (float*)d_out;

    k_prep<<<NSEG, 256>>>(parsing);
    k_pool<<<NSEG * NCH, 512>>>(xs);
    k_fcA <<<NSEG * (2048 / 8), 256>>>(fcA_w, fcA_b);
    k_fcB <<<NSEG * (512  / 8), 256>>>(fcB_w, fcB_b);
    k_fcC <<<NSEG * (512  / 8), 256>>>(fcC_w, fcC_b, out);
    k_p1  <<<NSEG * (256  / 8), 256>>>(p1_w, p1_b, out);
    k_p2  <<<NSEG * (128  / 8), 256>>>(p2_w, p2_b, out);
    k_p3  <<<NSEG * (64   / 8), 256>>>(p3_w, p3_b, out);
}